// round 4
// baseline (speedup 1.0000x reference)
#include <cuda_runtime.h>
#include <cuda_fp16.h>
#include <cstdint>

// Instant-NGP hash grid encode, round 4.
//  - fp16 tables; table A (natural) covers x-pair masks 1,3 in one 16B slot.
//  - table B (8-blocks reordered [0,7,1,6,2,5,3,4]) covers mask 7.
//  - mask>=15 (12.5%): predicated extra partner load from A.
//  - dense level 0 cached in shared memory (LDS gathers).
//  - coalesced output via warp-local smem transpose.

static constexpr int NPTS = 524288;
static constexpr unsigned HASH_MASK = (1u << 19) - 1u;
static constexpr unsigned P1 = 2654435761u;
static constexpr unsigned P2 = 805459861u;

static constexpr int DENSE_N = 4913 + 35937 + 274625;   // 315475
static constexpr int L0_N = 4913;
static constexpr int NH = 13 << 19;                      // hashed entries

// device-global tables (allocation-free scratch)
__device__ __align__(16) uint32_t g_A[NH];      // half2 entries, natural order
__device__ __align__(16) uint32_t g_B[NH];      // half2 entries, mask-7 pairing order
__device__ __align__(16) uint2    g_dense_h[DENSE_N];  // {e[i], e[i+1]} as halves

__device__ __forceinline__ uint32_t pack_h2(float2 v) {
    __half2 h = __float22half2_rn(v);
    return *reinterpret_cast<uint32_t*>(&h);
}
__device__ __forceinline__ float2 unpack_h2(uint32_t u) {
    __half2 h = *reinterpret_cast<__half2*>(&u);
    return __half22float2(h);
}
__device__ __forceinline__ float2 pick4(uint4 q, unsigned i) {
    const uint32_t lo = (i & 2u) ? q.z : q.x;
    const uint32_t hi = (i & 2u) ? q.w : q.y;
    return unpack_h2((i & 1u) ? hi : lo);
}

static constexpr int PREP_A = NH / 4;           // threads for A (4 entries each)
static constexpr int PREP_B = NH / 8;           // threads for B (8 entries each)
static constexpr int PREP_D = (DENSE_N + 1) / 2;

__global__ __launch_bounds__(256)
void prepass_kernel(const float2* __restrict__ emb)
{
    const int i = blockIdx.x * 256 + threadIdx.x;
    const float2* __restrict__ eh = emb + DENSE_N;

    if (i < PREP_A) {
        uint4 o;
        o.x = pack_h2(__ldg(eh + 4 * i + 0));
        o.y = pack_h2(__ldg(eh + 4 * i + 1));
        o.z = pack_h2(__ldg(eh + 4 * i + 2));
        o.w = pack_h2(__ldg(eh + 4 * i + 3));
        reinterpret_cast<uint4*>(g_A)[i] = o;
    } else if (i < PREP_A + PREP_B) {
        const int j = i - PREP_A;
        const float2* __restrict__ blk = eh + 8 * j;
        // B block order: positions [0..7] hold entries [0,7,1,6,2,5,3,4]
        uint4 o0, o1;
        o0.x = pack_h2(__ldg(blk + 0));
        o0.y = pack_h2(__ldg(blk + 7));
        o0.z = pack_h2(__ldg(blk + 1));
        o0.w = pack_h2(__ldg(blk + 6));
        o1.x = pack_h2(__ldg(blk + 2));
        o1.y = pack_h2(__ldg(blk + 5));
        o1.z = pack_h2(__ldg(blk + 3));
        o1.w = pack_h2(__ldg(blk + 4));
        reinterpret_cast<uint4*>(g_B)[2 * j]     = o0;
        reinterpret_cast<uint4*>(g_B)[2 * j + 1] = o1;
    } else {
        const int j = (i - PREP_A - PREP_B) * 2;
        if (j < DENSE_N) {
            const float2 a = __ldg(emb + j);
            const float2 b = __ldg(emb + j + 1);
            g_dense_h[j] = make_uint2(pack_h2(a), pack_h2(b));
            if (j + 1 < DENSE_N) {
                const float2 c = __ldg(emb + j + 2);
                g_dense_h[j + 1] = make_uint2(pack_h2(b), pack_h2(c));
            }
        }
    }
}

static constexpr int SMEM_L0_BYTES = 4928 * 4;              // 19712 (padded)
static constexpr int SMEM_TR_BYTES = 256 * 8 * 16;          // 32768
static constexpr int SMEM_TOTAL = SMEM_L0_BYTES + SMEM_TR_BYTES;  // 52480

__global__ __launch_bounds__(256, 4)
void hash_encode_kernel(const float* __restrict__ xin,
                        const float2* __restrict__ emb,
                        float4* __restrict__ out)
{
    extern __shared__ uint8_t dynsm[];
    uint32_t* s_l0 = reinterpret_cast<uint32_t*>(dynsm);
    float4*   s_tr = reinterpret_cast<float4*>(dynsm + SMEM_L0_BYTES);

    const unsigned tid  = threadIdx.x;
    const unsigned lane = tid & 31u;
    const int b = blockIdx.x * 256 + tid;

    // stage level-0 table (fp32 -> half2) into smem
    for (int i = (int)tid; i < L0_N; i += 256)
        s_l0[i] = pack_h2(__ldg(emb + i));
    __syncthreads();

    const float x = (xin[3 * b + 0] + 1.0f) * 0.5f;
    const float y = (xin[3 * b + 1] + 1.0f) * 0.5f;
    const float z = (xin[3 * b + 2] + 1.0f) * 0.5f;

    unsigned off = 0;
#pragma unroll
    for (int l = 0; l < 16; ++l) {
        const int res = 16 << l;
        const float fres = (float)res;

        const float px = x * fres, py = y * fres, pz = z * fres;
        const float gx = floorf(px), gy = floorf(py), gz = floorf(pz);
        const float tx = px - gx, ty = py - gy, tz = pz - gz;
        const unsigned ix = (unsigned)gx, iy = (unsigned)gy, iz = (unsigned)gz;

        float2 v000, v100, v010, v110, v001, v101, v011, v111;

        if (l == 0) {
            // smem gathers (res=16, s1=17, s2=289)
            const unsigned base = ix + iy * 17u + iz * 289u;
            v000 = unpack_h2(s_l0[base]);
            v100 = unpack_h2(s_l0[base + 1u]);
            v010 = unpack_h2(s_l0[base + 17u]);
            v110 = unpack_h2(s_l0[base + 18u]);
            v001 = unpack_h2(s_l0[base + 289u]);
            v101 = unpack_h2(s_l0[base + 290u]);
            v011 = unpack_h2(s_l0[base + 306u]);
            v111 = unpack_h2(s_l0[base + 307u]);
        } else if (l < 3) {
            const unsigned s1 = (unsigned)(res + 1);
            const unsigned s2 = s1 * s1;
            const unsigned base = off + ix + iy * s1 + iz * s2;
            const uint2 p0 = __ldg(g_dense_h + base);
            const uint2 p1 = __ldg(g_dense_h + base + s1);
            const uint2 p2 = __ldg(g_dense_h + base + s2);
            const uint2 p3 = __ldg(g_dense_h + base + s1 + s2);
            v000 = unpack_h2(p0.x);  v100 = unpack_h2(p0.y);
            v010 = unpack_h2(p1.x);  v110 = unpack_h2(p1.y);
            v001 = unpack_h2(p2.x);  v101 = unpack_h2(p2.y);
            v011 = unpack_h2(p3.x);  v111 = unpack_h2(p3.y);
        } else {
            const unsigned lvl = (unsigned)(l - 3);
            const uint4* __restrict__ TA =
                reinterpret_cast<const uint4*>(g_A) + ((size_t)lvl << 17);
            const uint4* __restrict__ TB =
                reinterpret_cast<const uint4*>(g_B) + ((size_t)lvl << 17);

            const unsigned hy0 = iy * P1, hy1 = hy0 + P1;
            const unsigned hz0 = iz * P2, hz1 = hz0 + P2;
            const unsigned a00 = hy0 ^ hz0, a10 = hy1 ^ hz0;
            const unsigned a01 = hy0 ^ hz1, a11 = hy1 ^ hz1;

            const unsigned mask = ix ^ (ix + 1u);
            const bool small = mask < 4u;
            const bool isB   = mask == 7u;
            const unsigned dp = small ? mask : 1u;   // in-slot partner xor
            const uint4* __restrict__ tb = isB ? TB : TA;

            const unsigned m00 = (ix ^ a00) & HASH_MASK;
            const unsigned m10 = (ix ^ a10) & HASH_MASK;
            const unsigned m01 = (ix ^ a01) & HASH_MASK;
            const unsigned m11 = (ix ^ a11) & HASH_MASK;

            // flat position: B-reordered for mask==7, natural otherwise
            const unsigned t0 = m00 & 7u, t1 = m10 & 7u, t2 = m01 & 7u, t3 = m11 & 7u;
            const unsigned p0 = (t0 < 4u) ? (t0 + t0) : (15u - (t0 + t0));
            const unsigned p1 = (t1 < 4u) ? (t1 + t1) : (15u - (t1 + t1));
            const unsigned p2 = (t2 < 4u) ? (t2 + t2) : (15u - (t2 + t2));
            const unsigned p3 = (t3 < 4u) ? (t3 + t3) : (15u - (t3 + t3));
            const unsigned f0 = isB ? ((m00 & ~7u) | p0) : m00;
            const unsigned f1 = isB ? ((m10 & ~7u) | p1) : m10;
            const unsigned f2 = isB ? ((m01 & ~7u) | p2) : m01;
            const unsigned f3 = isB ? ((m11 & ~7u) | p3) : m11;

            const uint4 Q0 = __ldg(tb + (f0 >> 2));
            const uint4 Q1 = __ldg(tb + (f1 >> 2));
            const uint4 Q2 = __ldg(tb + (f2 >> 2));
            const uint4 Q3 = __ldg(tb + (f3 >> 2));

            v000 = pick4(Q0, f0 & 3u);  v100 = pick4(Q0, (f0 & 3u) ^ dp);
            v010 = pick4(Q1, f1 & 3u);  v110 = pick4(Q1, (f1 & 3u) ^ dp);
            v001 = pick4(Q2, f2 & 3u);  v101 = pick4(Q2, (f2 & 3u) ^ dp);
            v011 = pick4(Q3, f3 & 3u);  v111 = pick4(Q3, (f3 & 3u) ^ dp);

            if (mask > 7u) {   // 12.5% of lanes: partner in a far slot, fetch from A
                const unsigned n00 = (m00 ^ mask) & HASH_MASK;
                const unsigned n10 = (m10 ^ mask) & HASH_MASK;
                const unsigned n01 = (m01 ^ mask) & HASH_MASK;
                const unsigned n11 = (m11 ^ mask) & HASH_MASK;
                const uint4 R0 = __ldg(TA + (n00 >> 2));
                const uint4 R1 = __ldg(TA + (n10 >> 2));
                const uint4 R2 = __ldg(TA + (n01 >> 2));
                const uint4 R3 = __ldg(TA + (n11 >> 2));
                v100 = pick4(R0, n00 & 3u);
                v110 = pick4(R1, n10 & 3u);
                v101 = pick4(R2, n01 & 3u);
                v111 = pick4(R3, n11 & 3u);
            }
        }

        const float ux = 1.0f - tx, uy = 1.0f - ty, uz = 1.0f - tz;
        const float w000 = ux * uy * uz;
        const float w100 = tx * uy * uz;
        const float w010 = ux * ty * uz;
        const float w110 = tx * ty * uz;
        const float w001 = ux * uy * tz;
        const float w101 = tx * uy * tz;
        const float w011 = ux * ty * tz;
        const float w111 = tx * ty * tz;

        float a = w000 * v000.x;
        float c = w000 * v000.y;
        a = fmaf(w100, v100.x, a);  c = fmaf(w100, v100.y, c);
        a = fmaf(w010, v010.x, a);  c = fmaf(w010, v010.y, c);
        a = fmaf(w110, v110.x, a);  c = fmaf(w110, v110.y, c);
        a = fmaf(w001, v001.x, a);  c = fmaf(w001, v001.y, c);
        a = fmaf(w101, v101.x, a);  c = fmaf(w101, v101.y, c);
        a = fmaf(w011, v011.x, a);  c = fmaf(w011, v011.y, c);
        a = fmaf(w111, v111.x, a);  c = fmaf(w111, v111.y, c);

        // stash into smem (xor swizzle, float4-granular)
        float2* cell = reinterpret_cast<float2*>(
            &s_tr[tid * 8 + (((unsigned)(l >> 1)) ^ (lane & 7u))]) + (l & 1);
        *cell = make_float2(a, c);

        off += (l < 3) ? (unsigned)((res + 1) * (res + 1) * (res + 1)) : 0u;
    }

    __syncwarp();

    // coalesced store: each warp writes its own contiguous 4KB output region
    const unsigned w = tid >> 5;
    float4* __restrict__ of4 = out + ((size_t)blockIdx.x * 256 + w * 32) * 8;
#pragma unroll
    for (int j = 0; j < 8; ++j) {
        const unsigned g  = (unsigned)j * 32u + lane;
        const unsigned p  = g >> 3;
        const unsigned c4 = g & 7u;
        of4[g] = s_tr[(w * 32 + p) * 8 + (c4 ^ (p & 7u))];
    }
}

extern "C" void kernel_launch(void* const* d_in, const int* in_sizes, int n_in,
                              void* d_out, int out_size)
{
    const float* xin;
    const float* emb;
    if (in_sizes[0] == NPTS * 3) {
        xin = (const float*)d_in[0];
        emb = (const float*)d_in[1];
    } else {
        xin = (const float*)d_in[1];
        emb = (const float*)d_in[0];
    }

    cudaFuncSetAttribute(hash_encode_kernel,
                         cudaFuncAttributeMaxDynamicSharedMemorySize, SMEM_TOTAL);

    const int prep_total = PREP_A + PREP_B + PREP_D;
    prepass_kernel<<<(prep_total + 255) / 256, 256>>>((const float2*)emb);

    hash_encode_kernel<<<NPTS / 256, 256, SMEM_TOTAL>>>(
        xin, (const float2*)emb, (float4*)d_out);
}